// round 15
// baseline (speedup 1.0000x reference)
#include <cuda_runtime.h>
#include <cuda_fp16.h>
#include <math.h>
#include <stdint.h>

// Problem constants
#define BATCH 8
#define CIN   384
#define OCH   512
#define NTOK  2304   // 48*48

#define NTHREADS 128
// Block tile 128x128, K-tile = 32 halves, warp tile 64x64 (2x2 warps)
#define SNT 40     // NT smem tile row stride (halves): [128 r][40]
#define STR 136    // TR smem tile row stride (halves): [32 k][136]
#define SLOT 5120  // halves per stage slot (10240 B)
#define SLOTB 10240
#define NSTAGE 4
#define SMEM_BYTES (2 * NSTAGE * SLOTB)   // 81920
#define MSPLIT 4   // K-splits for the M = Wq^T Wk GEMM

// Static scratch (no allocations allowed)
__device__ __half g_xh [(size_t)BATCH * CIN * NTOK];   // x half, [B][c][tok]
__device__ __half g_yh [(size_t)BATCH * CIN * NTOK];   // Y = M*X, [B][c][tok]
__device__ __half g_g  [(size_t)BATCH * NTOK * CIN];   // G = P' x^T, [B][tok][c]
__device__ __half g_p  [(size_t)BATCH * NTOK * NTOK];  // P' = exp(scores), half
__device__ __half g_ao [(size_t)BATCH * NTOK * OCH];   // [B][tok][och]
__device__ float  g_z  [(size_t)BATCH * NTOK];         // rowsum(P') via atomics
__device__ float  g_rv [(size_t)BATCH * NTOK];         // v[n] + c0 (row bias of S)
__device__ float  g_cu [(size_t)BATCH * NTOK];         // u[m]      (col bias of S)
__device__ __half g_wqh[(size_t)OCH * CIN];            // Wq half
__device__ __half g_wkh[(size_t)OCH * CIN];            // Wk half
__device__ __half g_wvh[(size_t)OCH * CIN];            // Wv half
__device__ __half g_woh[(size_t)OCH * OCH];            // Wo half
__device__ __half g_mp [(size_t)MSPLIT * CIN * CIN];   // M split-K partials
__device__ __half g_mh [(size_t)CIN * CIN];            // M = Wq^T Wk (half)
__device__ float  g_wv [CIN];                           // Wq^T bk
__device__ float  g_wu [CIN];                           // Wk^T bq
__device__ float  g_c0 [1];                             // bq . bk

// ---------------------------------------------------------------------------
// Helpers
// ---------------------------------------------------------------------------
__device__ __forceinline__ uint32_t smem_u32(const void* p) {
    uint32_t a;
    asm("{ .reg .u64 t; cvta.to.shared.u64 t, %1; cvt.u32.u64 %0, t; }" : "=r"(a) : "l"(p));
    return a;
}
__device__ __forceinline__ void ldsm4(uint32_t r[4], uint32_t addr) {
    asm volatile("ldmatrix.sync.aligned.m8n8.x4.shared.b16 {%0,%1,%2,%3}, [%4];"
                 : "=r"(r[0]), "=r"(r[1]), "=r"(r[2]), "=r"(r[3]) : "r"(addr));
}
__device__ __forceinline__ void ldsm4t(uint32_t r[4], uint32_t addr) {
    asm volatile("ldmatrix.sync.aligned.m8n8.x4.trans.shared.b16 {%0,%1,%2,%3}, [%4];"
                 : "=r"(r[0]), "=r"(r[1]), "=r"(r[2]), "=r"(r[3]) : "r"(addr));
}
__device__ __forceinline__ void mma16816(float c[4], const uint32_t a[4],
                                         uint32_t b0, uint32_t b1) {
    asm volatile(
        "mma.sync.aligned.m16n8k16.row.col.f32.f16.f16.f32 "
        "{%0,%1,%2,%3}, {%4,%5,%6,%7}, {%8,%9}, {%0,%1,%2,%3};"
        : "+f"(c[0]), "+f"(c[1]), "+f"(c[2]), "+f"(c[3])
        : "r"(a[0]), "r"(a[1]), "r"(a[2]), "r"(a[3]), "r"(b0), "r"(b1));
}
__device__ __forceinline__ void cp16(uint32_t saddr, const void* gaddr) {
    asm volatile("cp.async.cg.shared.global [%0], [%1], 16;" :: "r"(saddr), "l"(gaddr));
}
__device__ __forceinline__ void cp_commit() { asm volatile("cp.async.commit_group;"); }
template <int N>
__device__ __forceinline__ void cp_waitg() {
    asm volatile("cp.async.wait_group %0;" :: "n"(N) : "memory");
}

// ---------------------------------------------------------------------------
// cp.async staging. TRT=0: NT tile [128][SNT] from [r][k] src.
// TRT=1: TR tile [32][STR] from [k][r] src (r contiguous).
// ---------------------------------------------------------------------------
template <int TRT>
__device__ __forceinline__ void cp_stage(uint32_t sbase, const __half* __restrict__ S,
                                         int ld, int r0, int kt, int tid)
{
    if (TRT == 0) {
#pragma unroll
        for (int i = 0; i < 4; i++) {
            const int idx = tid + i * 128;
            const int r = idx >> 2, c8 = (idx & 3) * 8;
            cp16(sbase + (uint32_t)(r * SNT + c8) * 2, &S[(size_t)(r0 + r) * ld + kt + c8]);
        }
    } else {
#pragma unroll
        for (int i = 0; i < 4; i++) {
            const int idx = tid + i * 128;
            const int k = idx >> 4, c8 = (idx & 15) * 8;
            cp16(sbase + (uint32_t)(k * STR + c8) * 2, &S[(size_t)(kt + k) * ld + r0 + c8]);
        }
    }
}

// ---------------------------------------------------------------------------
// One 128x128x32 tile step. Warp tile 64x64 via m16n8k16 + ldmatrix.
// Mode: 0 = NT tile (ldsm4), 3 = TR tile (ldsm4t).
// ---------------------------------------------------------------------------
template <int AM, int BM>
__device__ __forceinline__ void compute_bk(uint32_t sa, uint32_t sb,
                                           float acc[4][8][4], int lane, int wm, int wn)
{
    constexpr bool ATR = (AM == 3), BTR = (BM == 3);
#pragma unroll
    for (int ks = 0; ks < 32; ks += 16) {
        uint32_t a[4][4];
#pragma unroll
        for (int mb = 0; mb < 4; mb++) {
            if (!ATR) {
                const int row = wm + mb * 16 + (lane & 15);
                const int col = ks + ((lane >> 4) << 3);
                ldsm4(a[mb], sa + (uint32_t)(row * SNT + col) * 2);
            } else {
                const int k   = ks + (lane & 7) + ((lane & 16) >> 1);
                const int col = wm + mb * 16 + (lane & 8);
                ldsm4t(a[mb], sa + (uint32_t)(k * STR + col) * 2);
            }
        }
        uint32_t bfr[4][4];
#pragma unroll
        for (int nb2 = 0; nb2 < 4; nb2++) {
            if (!BTR) {
                const int row = wn + nb2 * 16 + (lane & 15);
                const int col = ks + ((lane >> 4) << 3);
                ldsm4(bfr[nb2], sb + (uint32_t)(row * SNT + col) * 2);
            } else {
                const int k   = ks + (lane & 7) + (lane & 8);
                const int col = wn + nb2 * 16 + ((lane & 16) >> 1);
                ldsm4t(bfr[nb2], sb + (uint32_t)(k * STR + col) * 2);
            }
        }
#pragma unroll
        for (int mb = 0; mb < 4; mb++)
#pragma unroll
            for (int nb = 0; nb < 8; nb++) {
                uint32_t b0, b1;
                if (!BTR) { b0 = bfr[nb >> 1][nb & 1];       b1 = bfr[nb >> 1][(nb & 1) + 2]; }
                else      { b0 = bfr[nb >> 1][2 * (nb & 1)]; b1 = bfr[nb >> 1][2 * (nb & 1) + 1]; }
                mma16816(acc[mb][nb], a[mb], b0, b1);
            }
    }
}

// ---------------------------------------------------------------------------
// Universal batched all-f16 GEMM:
//   C[m][n] = f((acc + biases) * scale)
// AM/BM: 0 = f16 NT, 3 = f16 TR (both cp.async 4-stage).
// OUTH: 1 = half out. BIAS: 0 none, 1 row add, 2 col add, 3 row DIVIDE (by Z),
//       4 row add (bias) + col add (bias2),
//       5 row DIVIDE (by Z in bias) then col ADD (bias2) post-scale.
// EXPM: 1 = __expf after scale. SUMZ: 1 = atomic row sums into zsum.
// The z grid dim + (sA,sB,sC) strides also express split-K (slice offsets).
// ---------------------------------------------------------------------------
template <int AM, int BM, int OUTH, int BIAS, int EXPM, int SUMZ>
__global__ __launch_bounds__(NTHREADS, 2)
void hgemm(const __half* __restrict__ A, const __half* __restrict__ B, void* __restrict__ C,
           int K, int ldA, int ldB, int ldC,
           size_t sA, size_t sB, size_t sC,
           const float* __restrict__ bias, const float* __restrict__ bias2,
           float* __restrict__ zsum, size_t sBias, size_t sBias2, float scale)
{
    extern __shared__ __half dsm[];

    const int tid = threadIdx.x;
    const int warp = tid >> 5, lane = tid & 31;
    const int wm = (warp >> 1) * 64, wn = (warp & 1) * 64;
    const int b = blockIdx.z;
    const int row0 = blockIdx.y * 128;
    const int col0 = blockIdx.x * 128;

    const __half* Ab = A + (size_t)b * sA;
    const __half* Bb = B + (size_t)b * sB;
    const float* biasb  = bias  ? bias  + (size_t)b * sBias  : nullptr;
    const float* bias2b = bias2 ? bias2 + (size_t)b * sBias2 : nullptr;
    float* zsumb = zsum ? zsum + (size_t)b * sBias : nullptr;

    const uint32_t uA = smem_u32(dsm);
    const uint32_t uB = uA + NSTAGE * SLOTB;

    float acc[4][8][4];
#pragma unroll
    for (int i = 0; i < 4; i++)
#pragma unroll
        for (int j = 0; j < 8; j++)
#pragma unroll
            for (int q = 0; q < 4; q++) acc[i][j][q] = 0.f;

    const int T = K / 32;

    // Prologue: fill stages 0..2
#pragma unroll
    for (int s = 0; s < NSTAGE - 1; s++) {
        cp_stage<(AM == 3)>(uA + s * SLOTB, Ab, ldA, row0, s * 32, tid);
        cp_stage<(BM == 3)>(uB + s * SLOTB, Bb, ldB, col0, s * 32, tid);
        cp_commit();
    }

    for (int t = 0; t < T; t++) {
        cp_waitg<NSTAGE - 2>();
        __syncthreads();

        const int p = t & (NSTAGE - 1);
        const int tn = t + NSTAGE - 1;
        if (tn < T) {
            const int pn = tn & (NSTAGE - 1);
            cp_stage<(AM == 3)>(uA + pn * SLOTB, Ab, ldA, row0, tn * 32, tid);
            cp_stage<(BM == 3)>(uB + pn * SLOTB, Bb, ldB, col0, tn * 32, tid);
        }
        cp_commit();   // empty group at tail keeps FIFO accounting uniform

        compute_bk<AM, BM>(uA + p * SLOTB, uB + p * SLOTB, acc, lane, wm, wn);
    }

    // Epilogue
#pragma unroll
    for (int mb = 0; mb < 4; mb++) {
        const int m0 = row0 + wm + mb * 16 + (lane >> 2);
        const float ar0 = (BIAS == 1 || BIAS == 4) ? biasb[m0] : 0.f;
        const float ar1 = (BIAS == 1 || BIAS == 4) ? biasb[m0 + 8] : 0.f;
        const float rs0 = (BIAS == 3 || BIAS == 5) ? (1.0f / biasb[m0]) : 1.f;
        const float rs1 = (BIAS == 3 || BIAS == 5) ? (1.0f / biasb[m0 + 8]) : 1.f;
        float s0 = 0.f, s1 = 0.f;
#pragma unroll
        for (int nb = 0; nb < 8; nb++) {
            const int n = col0 + wn + nb * 8 + 2 * (lane & 3);
            float ac0 = 0.f, ac1 = 0.f;
            if (BIAS == 2) { ac0 = biasb[n]; ac1 = biasb[n + 1]; }
            if (BIAS == 4) { ac0 = bias2b[n]; ac1 = bias2b[n + 1]; }
            float pb0 = 0.f, pb1 = 0.f;
            if (BIAS == 5) { pb0 = bias2b[n]; pb1 = bias2b[n + 1]; }
            float v0 = (acc[mb][nb][0] + ar0 + ac0) * scale;
            float v1 = (acc[mb][nb][1] + ar0 + ac1) * scale;
            float v2 = (acc[mb][nb][2] + ar1 + ac0) * scale;
            float v3 = (acc[mb][nb][3] + ar1 + ac1) * scale;
            if (EXPM) { v0 = __expf(v0); v1 = __expf(v1); v2 = __expf(v2); v3 = __expf(v3); }
            if (BIAS == 3 || BIAS == 5) { v0 *= rs0; v1 *= rs0; v2 *= rs1; v3 *= rs1; }
            if (BIAS == 5) { v0 += pb0; v1 += pb1; v2 += pb0; v3 += pb1; }
            if (SUMZ) { s0 += v0 + v1; s1 += v2 + v3; }
            if (OUTH) {
                __half* Ch = (__half*)C + (size_t)b * sC;
                *reinterpret_cast<__half2*>(&Ch[(size_t)m0 * ldC + n])       = __floats2half2_rn(v0, v1);
                *reinterpret_cast<__half2*>(&Ch[(size_t)(m0 + 8) * ldC + n]) = __floats2half2_rn(v2, v3);
            } else {
                float* Cf = (float*)C + (size_t)b * sC;
                *reinterpret_cast<float2*>(&Cf[(size_t)m0 * ldC + n])       = make_float2(v0, v1);
                *reinterpret_cast<float2*>(&Cf[(size_t)(m0 + 8) * ldC + n]) = make_float2(v2, v3);
            }
        }
        if (SUMZ) {
            s0 += __shfl_xor_sync(0xffffffffu, s0, 1);
            s0 += __shfl_xor_sync(0xffffffffu, s0, 2);
            s1 += __shfl_xor_sync(0xffffffffu, s1, 1);
            s1 += __shfl_xor_sync(0xffffffffu, s1, 2);
            if ((lane & 3) == 0) {
                atomicAdd(&zsumb[m0], s0);
                atomicAdd(&zsumb[m0 + 8], s1);
            }
        }
    }
}

// ---------------------------------------------------------------------------
// Pack weights -> half; zero Z.
// ---------------------------------------------------------------------------
__global__ __launch_bounds__(256)
void pack_kernel(const float* __restrict__ Wq, const float* __restrict__ Wk,
                 const float* __restrict__ Wv, const float* __restrict__ Wo,
                 __half* __restrict__ wqh, __half* __restrict__ wkh,
                 __half* __restrict__ wvh, __half* __restrict__ woh,
                 float* __restrict__ Z)
{
    const int i = blockIdx.x * 256 + threadIdx.x;
    if (i < OCH * CIN) {
        wqh[i] = __float2half_rn(Wq[i]);
        wkh[i] = __float2half_rn(Wk[i]);
        wvh[i] = __float2half_rn(Wv[i]);
    }
    if (i < OCH * OCH) woh[i] = __float2half_rn(Wo[i]);
    if (i < BATCH * NTOK) Z[i] = 0.f;
}

// ---------------------------------------------------------------------------
// Reduce MSPLIT half partials -> half M. 8 halves (uint4) per thread.
// ---------------------------------------------------------------------------
__global__ __launch_bounds__(256)
void mred_kernel(const __half* __restrict__ mp, __half* __restrict__ mh)
{
    const int i = blockIdx.x * 256 + threadIdx.x;   // uint4 index
    constexpr int NU = CIN * CIN / 8;
    if (i >= NU) return;
    float acc[8];
#pragma unroll
    for (int q = 0; q < 8; q++) acc[q] = 0.f;
#pragma unroll
    for (int s = 0; s < MSPLIT; s++) {
        const uint4 u = reinterpret_cast<const uint4*>(mp + (size_t)s * CIN * CIN)[i];
        const __half2* h = reinterpret_cast<const __half2*>(&u);
#pragma unroll
        for (int q = 0; q < 4; q++) {
            const float2 f = __half22float2(h[q]);
            acc[2 * q] += f.x; acc[2 * q + 1] += f.y;
        }
    }
    uint4 o;
    __half2* oh = reinterpret_cast<__half2*>(&o);
#pragma unroll
    for (int q = 0; q < 4; q++) oh[q] = __floats2half2_rn(acc[2 * q], acc[2 * q + 1]);
    reinterpret_cast<uint4*>(mh)[i] = o;
}

// ---------------------------------------------------------------------------
// w_v = Wq^T bk, w_u = Wk^T bq, c0 = bq.bk
// grid = 3 blocks x 512 threads: 128 i-columns per block, 4 o-groups of 128.
// ---------------------------------------------------------------------------
__global__ __launch_bounds__(512)
void uvw_kernel(const float* __restrict__ Wq, const float* __restrict__ Wk,
                const float* __restrict__ bq, const float* __restrict__ bk,
                float* __restrict__ wv, float* __restrict__ wu, float* __restrict__ c0)
{
    __shared__ float sv[4][128], su[4][128], red[256];
    const int t = threadIdx.x & 127, g = threadIdx.x >> 7;
    const int i = blockIdx.x * 128 + t;

    float av = 0.f, au = 0.f;
#pragma unroll 4
    for (int o = g * 128; o < (g + 1) * 128; o++) {
        av += Wq[(size_t)o * CIN + i] * bk[o];
        au += Wk[(size_t)o * CIN + i] * bq[o];
    }
    sv[g][t] = av; su[g][t] = au;

    if (threadIdx.x < 256)
        red[threadIdx.x] = bq[threadIdx.x] * bk[threadIdx.x]
                         + bq[threadIdx.x + 256] * bk[threadIdx.x + 256];
    __syncthreads();

    if (g == 0) {
        wv[i] = sv[0][t] + sv[1][t] + sv[2][t] + sv[3][t];
        wu[i] = su[0][t] + su[1][t] + su[2][t] + su[3][t];
    }
    for (int s = 128; s > 0; s >>= 1) {
        if (threadIdx.x < s) red[threadIdx.x] += red[threadIdx.x + s];
        __syncthreads();
    }
    if (blockIdx.x == 0 && threadIdx.x == 0) c0[0] = red[0];
}

// ---------------------------------------------------------------------------
// Fused x convert + rank-1 terms. One pass over x:
//   xh = half(x); rv[b][n] = w_v.x_n + c0; cu[b][n] = w_u.x_n
// grid = B*NTOK/64 = 288 blocks x 512 threads: 64 tokens, 8 channel groups of 48.
// ---------------------------------------------------------------------------
__global__ __launch_bounds__(512)
void xuv_kernel(const float* __restrict__ x, __half* __restrict__ xh,
                const float* __restrict__ wv, const float* __restrict__ wu,
                const float* __restrict__ c0,
                float* __restrict__ rv, float* __restrict__ cu)
{
    __shared__ float swv[CIN], swu[CIN];
    __shared__ float redv[8][64], redu[8][64];
    const int tid = threadIdx.x;
    if (tid < CIN) { swv[tid] = wv[tid]; swu[tid] = wu[tid]; }
    __syncthreads();

    const int tile = blockIdx.x;
    const int b = tile / (NTOK / 64);
    const int n0 = (tile % (NTOK / 64)) * 64;
    const size_t base = (size_t)b * CIN * NTOK;
    const float* xb = x + base;
    __half* xhb = xh + base;
    const int t = tid & 63, g = tid >> 6;

    float sv = 0.f, su = 0.f;
#pragma unroll 6
    for (int c = g * 48; c < (g + 1) * 48; c++) {
        const size_t off = (size_t)c * NTOK + n0 + t;
        const float xv = xb[off];
        xhb[off] = __float2half_rn(xv);
        sv += swv[c] * xv;
        su += swu[c] * xv;
    }
    redv[g][t] = sv; redu[g][t] = su;
    __syncthreads();

    if (g == 0) {
        const int idx = b * NTOK + n0 + t;
        float av = 0.f, au = 0.f;
#pragma unroll
        for (int q = 0; q < 8; q++) { av += redv[q][t]; au += redu[q][t]; }
        rv[idx] = av + c0[0];
        cu[idx] = au;
    }
}

// ---------------------------------------------------------------------------
extern "C" void kernel_launch(void* const* d_in, const int* in_sizes, int n_in,
                              void* d_out, int out_size)
{
    const float* x  = (const float*)d_in[0];
    const float* Wq = (const float*)d_in[1];
    const float* bq = (const float*)d_in[2];
    const float* Wk = (const float*)d_in[3];
    const float* bk = (const float*)d_in[4];
    const float* Wv = (const float*)d_in[5];
    const float* bv = (const float*)d_in[6];
    const float* Wo = (const float*)d_in[7];
    const float* bo = (const float*)d_in[8];
    float* out = (float*)d_out;

    __half *xh, *yh, *gg, *p, *ao, *wqh, *wkh, *wvh, *woh, *mp, *mh;
    float *z, *rv, *cu, *wv, *wu, *c0;
    cudaGetSymbolAddress((void**)&xh,  g_xh);
    cudaGetSymbolAddress((void**)&yh,  g_yh);
    cudaGetSymbolAddress((void**)&gg,  g_g);
    cudaGetSymbolAddress((void**)&p,   g_p);
    cudaGetSymbolAddress((void**)&ao,  g_ao);
    cudaGetSymbolAddress((void**)&z,   g_z);
    cudaGetSymbolAddress((void**)&rv,  g_rv);
    cudaGetSymbolAddress((void**)&cu,  g_cu);
    cudaGetSymbolAddress((void**)&wqh, g_wqh);
    cudaGetSymbolAddress((void**)&wkh, g_wkh);
    cudaGetSymbolAddress((void**)&wvh, g_wvh);
    cudaGetSymbolAddress((void**)&woh, g_woh);
    cudaGetSymbolAddress((void**)&mp,  g_mp);
    cudaGetSymbolAddress((void**)&mh,  g_mh);
    cudaGetSymbolAddress((void**)&wv,  g_wv);
    cudaGetSymbolAddress((void**)&wu,  g_wu);
    cudaGetSymbolAddress((void**)&c0,  g_c0);

    cudaFuncSetAttribute(hgemm<3,3,1,0,0,0>, cudaFuncAttributeMaxDynamicSharedMemorySize, SMEM_BYTES);
    cudaFuncSetAttribute(hgemm<0,3,1,0,0,0>, cudaFuncAttributeMaxDynamicSharedMemorySize, SMEM_BYTES);
    cudaFuncSetAttribute(hgemm<3,3,1,4,1,1>, cudaFuncAttributeMaxDynamicSharedMemorySize, SMEM_BYTES);
    cudaFuncSetAttribute(hgemm<0,0,1,0,0,0>, cudaFuncAttributeMaxDynamicSharedMemorySize, SMEM_BYTES);
    cudaFuncSetAttribute(hgemm<0,0,1,5,0,0>, cudaFuncAttributeMaxDynamicSharedMemorySize, SMEM_BYTES);
    cudaFuncSetAttribute(hgemm<0,0,0,1,0,0>, cudaFuncAttributeMaxDynamicSharedMemorySize, SMEM_BYTES);

    const dim3 blk(NTHREADS);
    const size_t sX  = (size_t)CIN * NTOK;
    const size_t sY  = (size_t)CIN * NTOK;
    const size_t sG  = (size_t)NTOK * CIN;
    const size_t sS  = (size_t)NTOK * NTOK;
    const size_t sAO = (size_t)NTOK * OCH;
    const float scale = 0.044194173824159216f; // 1/sqrt(512)

    // 0) weight packing, rank-1 vectors, fused x-convert + rank-1 terms
    pack_kernel<<<(OCH * OCH + 255) / 256, 256>>>(Wq, Wk, Wv, Wo, wqh, wkh, wvh, woh, z);
    uvw_kernel<<<CIN / 128, 512>>>(Wq, Wk, bq, bk, wv, wu, c0);
    xuv_kernel<<<BATCH * NTOK / 64, 512>>>(x, xh, wv, wu, c0, rv, cu);

    // 1) M = Wq^T Wk, split-K over z (4 slices of 128), then reduce
    {
        dim3 g(CIN / 128, CIN / 128, MSPLIT);
        hgemm<3,3,1,0,0,0><<<g, blk, SMEM_BYTES>>>(wqh, wkh, mp, OCH / MSPLIT, CIN, CIN, CIN,
                                                   (size_t)(OCH / MSPLIT) * CIN,
                                                   (size_t)(OCH / MSPLIT) * CIN,
                                                   (size_t)CIN * CIN,
                                                   nullptr, nullptr, nullptr, 0, 0, 1.0f);
        mred_kernel<<<(CIN * CIN / 8 + 255) / 256, 256>>>(mp, mh);
    }
    // 2) Y[c][tok] = M x   (A = mh NT, B = xh TR)
    {
        dim3 g(NTOK / 128, CIN / 128, BATCH);
        hgemm<0,3,1,0,0,0><<<g, blk, SMEM_BYTES>>>(mh, xh, yh, CIN, CIN, NTOK, NTOK,
                                                   0, sX, sY, nullptr, nullptr, nullptr, 0, 0, 1.0f);
    }
    // 3) P' = exp(scale*(x^T Y + rv[n] + cu[m]))  (K=384, fused exp + atomic Z)
    {
        dim3 g(NTOK / 128, NTOK / 128, BATCH);
        hgemm<3,3,1,4,1,1><<<g, blk, SMEM_BYTES>>>(xh, yh, p, CIN, NTOK, NTOK, NTOK,
                                                   sX, sY, sS, rv, cu, z, NTOK, NTOK, scale);
    }
    // 4) G[tok][c] = P' x^T   (A = P' NT, B = xh NT: B[c][k]=x[c][tok k])
    {
        dim3 g(CIN / 128, NTOK / 128, BATCH);
        hgemm<0,0,1,0,0,0><<<g, blk, SMEM_BYTES>>>(p, xh, gg, NTOK, NTOK, NTOK, CIN,
                                                   sS, sX, sG, nullptr, nullptr, nullptr, 0, 0, 1.0f);
    }
    // 5) AO[tok][o] = (G Wv^T)/Z[tok] + bv[o]   (A = G NT, B = wvh NT, BIAS 5)
    {
        dim3 g(OCH / 128, NTOK / 128, BATCH);
        hgemm<0,0,1,5,0,0><<<g, blk, SMEM_BYTES>>>(gg, wvh, ao, CIN, CIN, CIN, OCH,
                                                   sG, 0, sAO, z, bv, nullptr, NTOK, 0, 1.0f);
    }
    // 6) out[och][tok] = Wo AO^T + bo
    {
        dim3 g(NTOK / 128, OCH / 128, BATCH);
        hgemm<0,0,0,1,0,0><<<g, blk, SMEM_BYTES>>>(woh, ao, out, OCH, OCH, OCH, NTOK,
                                                   0, sAO, (size_t)OCH * NTOK, bo, nullptr, nullptr, 0, 0, 1.0f);
    }
}

// round 16
// speedup vs baseline: 1.5979x; 1.5979x over previous
#include <cuda_runtime.h>
#include <cuda_fp16.h>
#include <math.h>
#include <stdint.h>

// Problem constants
#define BATCH 8
#define CIN   384
#define OCH   512
#define NTOK  2304   // 48*48

#define NTHREADS 128
// Block tile 128x128, K-tile = 32 halves, warp tile 64x64 (2x2 warps)
#define SNT 40     // NT smem tile row stride (halves): [128 r][40]
#define STR 136    // TR smem tile row stride (halves): [32 k][136]
#define SLOT 5120  // halves per stage slot (10240 B)
#define SLOTB 10240
#define NSTAGE 4
#define SMEM_BYTES (2 * NSTAGE * SLOTB)   // 81920
#define MSPLIT 4   // K-splits for the M = Wq^T Wk GEMM

// Static scratch (no allocations allowed)
__device__ __half g_xh [(size_t)BATCH * CIN * NTOK];   // x half, [B][c][tok]
__device__ __half g_yh [(size_t)BATCH * CIN * NTOK];   // Y = M*X, [B][c][tok]
__device__ __half g_vh [(size_t)BATCH * NTOK * OCH];   // V proj, [B][tok][och]
__device__ __half g_p  [(size_t)BATCH * NTOK * NTOK];  // P' = exp(scores), half
__device__ __half g_ao [(size_t)BATCH * NTOK * OCH];   // [B][tok][och]
__device__ float  g_z  [(size_t)BATCH * NTOK];         // rowsum(P') via atomics
__device__ float  g_rv [(size_t)BATCH * NTOK];         // v[n] + c0 (row bias of S)
__device__ float  g_cu [(size_t)BATCH * NTOK];         // u[m]      (col bias of S)
__device__ __half g_wqh[(size_t)OCH * CIN];            // Wq half
__device__ __half g_wkh[(size_t)OCH * CIN];            // Wk half
__device__ __half g_wvh[(size_t)OCH * CIN];            // Wv half
__device__ __half g_woh[(size_t)OCH * OCH];            // Wo half
__device__ __half g_mp [(size_t)MSPLIT * CIN * CIN];   // M split-K partials
__device__ __half g_mh [(size_t)CIN * CIN];            // M = Wq^T Wk (half)
__device__ float  g_wv [CIN];                           // Wq^T bk
__device__ float  g_wu [CIN];                           // Wk^T bq
__device__ float  g_c0 [1];                             // bq . bk

// ---------------------------------------------------------------------------
// Helpers
// ---------------------------------------------------------------------------
__device__ __forceinline__ uint32_t smem_u32(const void* p) {
    uint32_t a;
    asm("{ .reg .u64 t; cvta.to.shared.u64 t, %1; cvt.u32.u64 %0, t; }" : "=r"(a) : "l"(p));
    return a;
}
__device__ __forceinline__ void ldsm4(uint32_t r[4], uint32_t addr) {
    asm volatile("ldmatrix.sync.aligned.m8n8.x4.shared.b16 {%0,%1,%2,%3}, [%4];"
                 : "=r"(r[0]), "=r"(r[1]), "=r"(r[2]), "=r"(r[3]) : "r"(addr));
}
__device__ __forceinline__ void ldsm4t(uint32_t r[4], uint32_t addr) {
    asm volatile("ldmatrix.sync.aligned.m8n8.x4.trans.shared.b16 {%0,%1,%2,%3}, [%4];"
                 : "=r"(r[0]), "=r"(r[1]), "=r"(r[2]), "=r"(r[3]) : "r"(addr));
}
__device__ __forceinline__ void mma16816(float c[4], const uint32_t a[4],
                                         uint32_t b0, uint32_t b1) {
    asm volatile(
        "mma.sync.aligned.m16n8k16.row.col.f32.f16.f16.f32 "
        "{%0,%1,%2,%3}, {%4,%5,%6,%7}, {%8,%9}, {%0,%1,%2,%3};"
        : "+f"(c[0]), "+f"(c[1]), "+f"(c[2]), "+f"(c[3])
        : "r"(a[0]), "r"(a[1]), "r"(a[2]), "r"(a[3]), "r"(b0), "r"(b1));
}
__device__ __forceinline__ void cp16(uint32_t saddr, const void* gaddr) {
    asm volatile("cp.async.cg.shared.global [%0], [%1], 16;" :: "r"(saddr), "l"(gaddr));
}
__device__ __forceinline__ void cp_commit() { asm volatile("cp.async.commit_group;"); }
template <int N>
__device__ __forceinline__ void cp_waitg() {
    asm volatile("cp.async.wait_group %0;" :: "n"(N) : "memory");
}

// ---------------------------------------------------------------------------
// cp.async staging. TRT=0: NT tile [128][SNT] from [r][k] src.
// TRT=1: TR tile [32][STR] from [k][r] src (r contiguous).
// ---------------------------------------------------------------------------
template <int TRT>
__device__ __forceinline__ void cp_stage(uint32_t sbase, const __half* __restrict__ S,
                                         int ld, int r0, int kt, int tid)
{
    if (TRT == 0) {
#pragma unroll
        for (int i = 0; i < 4; i++) {
            const int idx = tid + i * 128;
            const int r = idx >> 2, c8 = (idx & 3) * 8;
            cp16(sbase + (uint32_t)(r * SNT + c8) * 2, &S[(size_t)(r0 + r) * ld + kt + c8]);
        }
    } else {
#pragma unroll
        for (int i = 0; i < 4; i++) {
            const int idx = tid + i * 128;
            const int k = idx >> 4, c8 = (idx & 15) * 8;
            cp16(sbase + (uint32_t)(k * STR + c8) * 2, &S[(size_t)(kt + k) * ld + r0 + c8]);
        }
    }
}

// ---------------------------------------------------------------------------
// One 128x128x32 tile step. Warp tile 64x64 via m16n8k16 + ldmatrix.
// Mode: 0 = NT tile (ldsm4), 3 = TR tile (ldsm4t).
// ---------------------------------------------------------------------------
template <int AM, int BM>
__device__ __forceinline__ void compute_bk(uint32_t sa, uint32_t sb,
                                           float acc[4][8][4], int lane, int wm, int wn)
{
    constexpr bool ATR = (AM == 3), BTR = (BM == 3);
#pragma unroll
    for (int ks = 0; ks < 32; ks += 16) {
        uint32_t a[4][4];
#pragma unroll
        for (int mb = 0; mb < 4; mb++) {
            if (!ATR) {
                const int row = wm + mb * 16 + (lane & 15);
                const int col = ks + ((lane >> 4) << 3);
                ldsm4(a[mb], sa + (uint32_t)(row * SNT + col) * 2);
            } else {
                const int k   = ks + (lane & 7) + ((lane & 16) >> 1);
                const int col = wm + mb * 16 + (lane & 8);
                ldsm4t(a[mb], sa + (uint32_t)(k * STR + col) * 2);
            }
        }
        uint32_t bfr[4][4];
#pragma unroll
        for (int nb2 = 0; nb2 < 4; nb2++) {
            if (!BTR) {
                const int row = wn + nb2 * 16 + (lane & 15);
                const int col = ks + ((lane >> 4) << 3);
                ldsm4(bfr[nb2], sb + (uint32_t)(row * SNT + col) * 2);
            } else {
                const int k   = ks + (lane & 7) + (lane & 8);
                const int col = wn + nb2 * 16 + ((lane & 16) >> 1);
                ldsm4t(bfr[nb2], sb + (uint32_t)(k * STR + col) * 2);
            }
        }
#pragma unroll
        for (int mb = 0; mb < 4; mb++)
#pragma unroll
            for (int nb = 0; nb < 8; nb++) {
                uint32_t b0, b1;
                if (!BTR) { b0 = bfr[nb >> 1][nb & 1];       b1 = bfr[nb >> 1][(nb & 1) + 2]; }
                else      { b0 = bfr[nb >> 1][2 * (nb & 1)]; b1 = bfr[nb >> 1][2 * (nb & 1) + 1]; }
                mma16816(acc[mb][nb], a[mb], b0, b1);
            }
    }
}

// ---------------------------------------------------------------------------
// Universal batched all-f16 GEMM:
//   C[m][n] = f((acc + biases) * scale)
// AM/BM: 0 = f16 NT, 3 = f16 TR (both cp.async 4-stage).
// OUTH: 1 = half out. BIAS: 0 none, 1 row add, 2 col add, 3 row DIVIDE (by Z),
//       4 row add (bias) + col add (bias2).
// EXPM: 1 = __expf after scale. SUMZ: 1 = atomic row sums into zsum.
// The z grid dim + (sA,sB,sC) strides also express split-K (slice offsets).
// ---------------------------------------------------------------------------
template <int AM, int BM, int OUTH, int BIAS, int EXPM, int SUMZ>
__global__ __launch_bounds__(NTHREADS, 2)
void hgemm(const __half* __restrict__ A, const __half* __restrict__ B, void* __restrict__ C,
           int K, int ldA, int ldB, int ldC,
           size_t sA, size_t sB, size_t sC,
           const float* __restrict__ bias, const float* __restrict__ bias2,
           float* __restrict__ zsum, size_t sBias, float scale)
{
    extern __shared__ __half dsm[];

    const int tid = threadIdx.x;
    const int warp = tid >> 5, lane = tid & 31;
    const int wm = (warp >> 1) * 64, wn = (warp & 1) * 64;
    const int b = blockIdx.z;
    const int row0 = blockIdx.y * 128;
    const int col0 = blockIdx.x * 128;

    const __half* Ab = A + (size_t)b * sA;
    const __half* Bb = B + (size_t)b * sB;
    const float* biasb  = bias  ? bias  + (size_t)b * sBias : nullptr;
    const float* bias2b = bias2 ? bias2 + (size_t)b * sBias : nullptr;
    float* zsumb = zsum ? zsum + (size_t)b * sBias : nullptr;

    const uint32_t uA = smem_u32(dsm);
    const uint32_t uB = uA + NSTAGE * SLOTB;

    float acc[4][8][4];
#pragma unroll
    for (int i = 0; i < 4; i++)
#pragma unroll
        for (int j = 0; j < 8; j++)
#pragma unroll
            for (int q = 0; q < 4; q++) acc[i][j][q] = 0.f;

    const int T = K / 32;

    // Prologue: fill stages 0..2
#pragma unroll
    for (int s = 0; s < NSTAGE - 1; s++) {
        cp_stage<(AM == 3)>(uA + s * SLOTB, Ab, ldA, row0, s * 32, tid);
        cp_stage<(BM == 3)>(uB + s * SLOTB, Bb, ldB, col0, s * 32, tid);
        cp_commit();
    }

    for (int t = 0; t < T; t++) {
        cp_waitg<NSTAGE - 2>();
        __syncthreads();

        const int p = t & (NSTAGE - 1);
        const int tn = t + NSTAGE - 1;
        if (tn < T) {
            const int pn = tn & (NSTAGE - 1);
            cp_stage<(AM == 3)>(uA + pn * SLOTB, Ab, ldA, row0, tn * 32, tid);
            cp_stage<(BM == 3)>(uB + pn * SLOTB, Bb, ldB, col0, tn * 32, tid);
        }
        cp_commit();   // empty group at tail keeps FIFO accounting uniform

        compute_bk<AM, BM>(uA + p * SLOTB, uB + p * SLOTB, acc, lane, wm, wn);
    }

    // Epilogue
#pragma unroll
    for (int mb = 0; mb < 4; mb++) {
        const int m0 = row0 + wm + mb * 16 + (lane >> 2);
        const float ar0 = (BIAS == 1 || BIAS == 4) ? biasb[m0] : 0.f;
        const float ar1 = (BIAS == 1 || BIAS == 4) ? biasb[m0 + 8] : 0.f;
        const float rs0 = (BIAS == 3) ? (1.0f / biasb[m0]) : 1.f;
        const float rs1 = (BIAS == 3) ? (1.0f / biasb[m0 + 8]) : 1.f;
        float s0 = 0.f, s1 = 0.f;
#pragma unroll
        for (int nb = 0; nb < 8; nb++) {
            const int n = col0 + wn + nb * 8 + 2 * (lane & 3);
            float ac0 = 0.f, ac1 = 0.f;
            if (BIAS == 2) { ac0 = biasb[n]; ac1 = biasb[n + 1]; }
            if (BIAS == 4) { ac0 = bias2b[n]; ac1 = bias2b[n + 1]; }
            float v0 = (acc[mb][nb][0] + ar0 + ac0) * scale;
            float v1 = (acc[mb][nb][1] + ar0 + ac1) * scale;
            float v2 = (acc[mb][nb][2] + ar1 + ac0) * scale;
            float v3 = (acc[mb][nb][3] + ar1 + ac1) * scale;
            if (EXPM) { v0 = __expf(v0); v1 = __expf(v1); v2 = __expf(v2); v3 = __expf(v3); }
            if (BIAS == 3) { v0 *= rs0; v1 *= rs0; v2 *= rs1; v3 *= rs1; }
            if (SUMZ) { s0 += v0 + v1; s1 += v2 + v3; }
            if (OUTH) {
                __half* Ch = (__half*)C + (size_t)b * sC;
                *reinterpret_cast<__half2*>(&Ch[(size_t)m0 * ldC + n])       = __floats2half2_rn(v0, v1);
                *reinterpret_cast<__half2*>(&Ch[(size_t)(m0 + 8) * ldC + n]) = __floats2half2_rn(v2, v3);
            } else {
                float* Cf = (float*)C + (size_t)b * sC;
                *reinterpret_cast<float2*>(&Cf[(size_t)m0 * ldC + n])       = make_float2(v0, v1);
                *reinterpret_cast<float2*>(&Cf[(size_t)(m0 + 8) * ldC + n]) = make_float2(v2, v3);
            }
        }
        if (SUMZ) {
            s0 += __shfl_xor_sync(0xffffffffu, s0, 1);
            s0 += __shfl_xor_sync(0xffffffffu, s0, 2);
            s1 += __shfl_xor_sync(0xffffffffu, s1, 1);
            s1 += __shfl_xor_sync(0xffffffffu, s1, 2);
            if ((lane & 3) == 0) {
                atomicAdd(&zsumb[m0], s0);
                atomicAdd(&zsumb[m0 + 8], s1);
            }
        }
    }
}

// ---------------------------------------------------------------------------
// Pack weights -> half; zero Z.
// ---------------------------------------------------------------------------
__global__ __launch_bounds__(256)
void pack_kernel(const float* __restrict__ Wq, const float* __restrict__ Wk,
                 const float* __restrict__ Wv, const float* __restrict__ Wo,
                 __half* __restrict__ wqh, __half* __restrict__ wkh,
                 __half* __restrict__ wvh, __half* __restrict__ woh,
                 float* __restrict__ Z)
{
    const int i = blockIdx.x * 256 + threadIdx.x;
    if (i < OCH * CIN) {
        wqh[i] = __float2half_rn(Wq[i]);
        wkh[i] = __float2half_rn(Wk[i]);
        wvh[i] = __float2half_rn(Wv[i]);
    }
    if (i < OCH * OCH) woh[i] = __float2half_rn(Wo[i]);
    if (i < BATCH * NTOK) Z[i] = 0.f;
}

// ---------------------------------------------------------------------------
// Reduce MSPLIT half partials -> half M. 8 halves (uint4) per thread.
// ---------------------------------------------------------------------------
__global__ __launch_bounds__(256)
void mred_kernel(const __half* __restrict__ mp, __half* __restrict__ mh)
{
    const int i = blockIdx.x * 256 + threadIdx.x;   // uint4 index
    constexpr int NU = CIN * CIN / 8;
    if (i >= NU) return;
    float acc[8];
#pragma unroll
    for (int q = 0; q < 8; q++) acc[q] = 0.f;
#pragma unroll
    for (int s = 0; s < MSPLIT; s++) {
        const uint4 u = reinterpret_cast<const uint4*>(mp + (size_t)s * CIN * CIN)[i];
        const __half2* h = reinterpret_cast<const __half2*>(&u);
#pragma unroll
        for (int q = 0; q < 4; q++) {
            const float2 f = __half22float2(h[q]);
            acc[2 * q] += f.x; acc[2 * q + 1] += f.y;
        }
    }
    uint4 o;
    __half2* oh = reinterpret_cast<__half2*>(&o);
#pragma unroll
    for (int q = 0; q < 4; q++) oh[q] = __floats2half2_rn(acc[2 * q], acc[2 * q + 1]);
    reinterpret_cast<uint4*>(mh)[i] = o;
}

// ---------------------------------------------------------------------------
// w_v = Wq^T bk, w_u = Wk^T bq, c0 = bq.bk
// grid = 3 blocks x 512 threads: 128 i-columns per block, 4 o-groups of 128.
// ---------------------------------------------------------------------------
__global__ __launch_bounds__(512)
void uvw_kernel(const float* __restrict__ Wq, const float* __restrict__ Wk,
                const float* __restrict__ bq, const float* __restrict__ bk,
                float* __restrict__ wv, float* __restrict__ wu, float* __restrict__ c0)
{
    __shared__ float sv[4][128], su[4][128], red[256];
    const int t = threadIdx.x & 127, g = threadIdx.x >> 7;
    const int i = blockIdx.x * 128 + t;

    float av = 0.f, au = 0.f;
#pragma unroll 4
    for (int o = g * 128; o < (g + 1) * 128; o++) {
        av += Wq[(size_t)o * CIN + i] * bk[o];
        au += Wk[(size_t)o * CIN + i] * bq[o];
    }
    sv[g][t] = av; su[g][t] = au;

    if (threadIdx.x < 256)
        red[threadIdx.x] = bq[threadIdx.x] * bk[threadIdx.x]
                         + bq[threadIdx.x + 256] * bk[threadIdx.x + 256];
    __syncthreads();

    if (g == 0) {
        wv[i] = sv[0][t] + sv[1][t] + sv[2][t] + sv[3][t];
        wu[i] = su[0][t] + su[1][t] + su[2][t] + su[3][t];
    }
    for (int s = 128; s > 0; s >>= 1) {
        if (threadIdx.x < s) red[threadIdx.x] += red[threadIdx.x + s];
        __syncthreads();
    }
    if (blockIdx.x == 0 && threadIdx.x == 0) c0[0] = red[0];
}

// ---------------------------------------------------------------------------
// Fused x convert + rank-1 terms. One pass over x:
//   xh = half(x); rv[b][n] = w_v.x_n + c0; cu[b][n] = w_u.x_n
// grid = B*NTOK/64 = 288 blocks x 512 threads: 64 tokens, 8 channel groups of 48.
// ---------------------------------------------------------------------------
__global__ __launch_bounds__(512)
void xuv_kernel(const float* __restrict__ x, __half* __restrict__ xh,
                const float* __restrict__ wv, const float* __restrict__ wu,
                const float* __restrict__ c0,
                float* __restrict__ rv, float* __restrict__ cu)
{
    __shared__ float swv[CIN], swu[CIN];
    __shared__ float redv[8][64], redu[8][64];
    const int tid = threadIdx.x;
    if (tid < CIN) { swv[tid] = wv[tid]; swu[tid] = wu[tid]; }
    __syncthreads();

    const int tile = blockIdx.x;
    const int b = tile / (NTOK / 64);
    const int n0 = (tile % (NTOK / 64)) * 64;
    const size_t base = (size_t)b * CIN * NTOK;
    const float* xb = x + base;
    __half* xhb = xh + base;
    const int t = tid & 63, g = tid >> 6;

    float sv = 0.f, su = 0.f;
#pragma unroll 6
    for (int c = g * 48; c < (g + 1) * 48; c++) {
        const size_t off = (size_t)c * NTOK + n0 + t;
        const float xv = xb[off];
        xhb[off] = __float2half_rn(xv);
        sv += swv[c] * xv;
        su += swu[c] * xv;
    }
    redv[g][t] = sv; redu[g][t] = su;
    __syncthreads();

    if (g == 0) {
        const int idx = b * NTOK + n0 + t;
        float av = 0.f, au = 0.f;
#pragma unroll
        for (int q = 0; q < 8; q++) { av += redv[q][t]; au += redu[q][t]; }
        rv[idx] = av + c0[0];
        cu[idx] = au;
    }
}

// ---------------------------------------------------------------------------
extern "C" void kernel_launch(void* const* d_in, const int* in_sizes, int n_in,
                              void* d_out, int out_size)
{
    const float* x  = (const float*)d_in[0];
    const float* Wq = (const float*)d_in[1];
    const float* bq = (const float*)d_in[2];
    const float* Wk = (const float*)d_in[3];
    const float* bk = (const float*)d_in[4];
    const float* Wv = (const float*)d_in[5];
    const float* bv = (const float*)d_in[6];
    const float* Wo = (const float*)d_in[7];
    const float* bo = (const float*)d_in[8];
    float* out = (float*)d_out;

    __half *xh, *yh, *vh, *p, *ao, *wqh, *wkh, *wvh, *woh, *mp, *mh;
    float *z, *rv, *cu, *wv, *wu, *c0;
    cudaGetSymbolAddress((void**)&xh,  g_xh);
    cudaGetSymbolAddress((void**)&yh,  g_yh);
    cudaGetSymbolAddress((void**)&vh,  g_vh);
    cudaGetSymbolAddress((void**)&p,   g_p);
    cudaGetSymbolAddress((void**)&ao,  g_ao);
    cudaGetSymbolAddress((void**)&z,   g_z);
    cudaGetSymbolAddress((void**)&rv,  g_rv);
    cudaGetSymbolAddress((void**)&cu,  g_cu);
    cudaGetSymbolAddress((void**)&wqh, g_wqh);
    cudaGetSymbolAddress((void**)&wkh, g_wkh);
    cudaGetSymbolAddress((void**)&wvh, g_wvh);
    cudaGetSymbolAddress((void**)&woh, g_woh);
    cudaGetSymbolAddress((void**)&mp,  g_mp);
    cudaGetSymbolAddress((void**)&mh,  g_mh);
    cudaGetSymbolAddress((void**)&wv,  g_wv);
    cudaGetSymbolAddress((void**)&wu,  g_wu);
    cudaGetSymbolAddress((void**)&c0,  g_c0);

    cudaFuncSetAttribute(hgemm<3,3,1,0,0,0>, cudaFuncAttributeMaxDynamicSharedMemorySize, SMEM_BYTES);
    cudaFuncSetAttribute(hgemm<3,0,1,2,0,0>, cudaFuncAttributeMaxDynamicSharedMemorySize, SMEM_BYTES);
    cudaFuncSetAttribute(hgemm<0,3,1,0,0,0>, cudaFuncAttributeMaxDynamicSharedMemorySize, SMEM_BYTES);
    cudaFuncSetAttribute(hgemm<3,3,1,4,1,1>, cudaFuncAttributeMaxDynamicSharedMemorySize, SMEM_BYTES);
    cudaFuncSetAttribute(hgemm<0,3,1,3,0,0>, cudaFuncAttributeMaxDynamicSharedMemorySize, SMEM_BYTES);
    cudaFuncSetAttribute(hgemm<0,0,0,1,0,0>, cudaFuncAttributeMaxDynamicSharedMemorySize, SMEM_BYTES);

    const dim3 blk(NTHREADS);
    const size_t sX  = (size_t)CIN * NTOK;
    const size_t sY  = (size_t)CIN * NTOK;
    const size_t sV  = (size_t)NTOK * OCH;
    const size_t sS  = (size_t)NTOK * NTOK;
    const size_t sAO = (size_t)NTOK * OCH;
    const float scale = 0.044194173824159216f; // 1/sqrt(512)

    // 0) weight packing, rank-1 vectors, fused x-convert + rank-1 terms
    pack_kernel<<<(OCH * OCH + 255) / 256, 256>>>(Wq, Wk, Wv, Wo, wqh, wkh, wvh, woh, z);
    uvw_kernel<<<CIN / 128, 512>>>(Wq, Wk, bq, bk, wv, wu, c0);
    xuv_kernel<<<BATCH * NTOK / 64, 512>>>(x, xh, wv, wu, c0, rv, cu);

    // 1) M = Wq^T Wk, split-K over z (4 slices of 128), then reduce
    {
        dim3 g(CIN / 128, CIN / 128, MSPLIT);
        hgemm<3,3,1,0,0,0><<<g, blk, SMEM_BYTES>>>(wqh, wkh, mp, OCH / MSPLIT, CIN, CIN, CIN,
                                                   (size_t)(OCH / MSPLIT) * CIN,
                                                   (size_t)(OCH / MSPLIT) * CIN,
                                                   (size_t)CIN * CIN,
                                                   nullptr, nullptr, nullptr, 0, 1.0f);
        mred_kernel<<<(CIN * CIN / 8 + 255) / 256, 256>>>(mp, mh);
    }
    // 2) V[tok][och] = x^T Wv^T + bv  (A = xh TR, B = wvh NT, col bias)
    {
        dim3 g(OCH / 128, NTOK / 128, BATCH);
        hgemm<3,0,1,2,0,0><<<g, blk, SMEM_BYTES>>>(xh, wvh, vh, CIN, NTOK, CIN, OCH,
                                                   sX, 0, sV, bv, nullptr, nullptr, 0, 1.0f);
    }
    // 3) Y[c][tok] = M x   (A = mh NT, B = xh TR)
    {
        dim3 g(NTOK / 128, CIN / 128, BATCH);
        hgemm<0,3,1,0,0,0><<<g, blk, SMEM_BYTES>>>(mh, xh, yh, CIN, CIN, NTOK, NTOK,
                                                   0, sX, sY, nullptr, nullptr, nullptr, 0, 1.0f);
    }
    // 4) P' = exp(scale*(x^T Y + rv[n] + cu[m]))  (K=384, fused exp + atomic Z)
    {
        dim3 g(NTOK / 128, NTOK / 128, BATCH);
        hgemm<3,3,1,4,1,1><<<g, blk, SMEM_BYTES>>>(xh, yh, p, CIN, NTOK, NTOK, NTOK,
                                                   sX, sY, sS, rv, cu, z, NTOK, scale);
    }
    // 5) AO[tok][och] = (P' V) / Z[tok]   (B = vh TR)
    {
        dim3 g(OCH / 128, NTOK / 128, BATCH);
        hgemm<0,3,1,3,0,0><<<g, blk, SMEM_BYTES>>>(p, vh, ao, NTOK, NTOK, OCH, OCH,
                                                   sS, sV, sAO, z, nullptr, nullptr, NTOK, 1.0f);
    }
    // 6) out[och][tok] = Wo AO^T + bo
    {
        dim3 g(NTOK / 128, OCH / 128, BATCH);
        hgemm<0,0,0,1,0,0><<<g, blk, SMEM_BYTES>>>(woh, ao, out, OCH, OCH, OCH, NTOK,
                                                   0, sAO, (size_t)OCH * NTOK, bo, nullptr, nullptr, 0, 1.0f);
    }
}

// round 17
// speedup vs baseline: 1.6463x; 1.0302x over previous
#include <cuda_runtime.h>
#include <cuda_fp16.h>
#include <math.h>
#include <stdint.h>

// Problem constants
#define BATCH 8
#define CIN   384
#define OCH   512
#define NTOK  2304   // 48*48

#define NTHREADS 128
// Block tile 128x128, K-tile = 32 halves, warp tile 64x64 (2x2 warps)
#define SNT 40     // NT smem tile row stride (halves): [128 r][40]
#define STR 136    // TR smem tile row stride (halves): [32 k][136]
#define SLOT 5120  // halves per stage slot (10240 B)
#define SLOTB 10240
#define NSTAGE 4
#define SMEM_BYTES (2 * NSTAGE * SLOTB)   // 81920
#define MSPLIT 4   // K-splits for the M = Wq^T Wk GEMM

// Static scratch (no allocations allowed)
__device__ __half g_xh [(size_t)BATCH * CIN * NTOK];   // x half, [B][c][tok]
__device__ __half g_yh [(size_t)BATCH * CIN * NTOK];   // Y = M*X, [B][c][tok]
__device__ __half g_vh [(size_t)BATCH * NTOK * OCH];   // V proj, [B][tok][och]
__device__ __half g_p  [(size_t)BATCH * NTOK * NTOK];  // P' = exp(scores), half
__device__ __half g_ao [(size_t)BATCH * NTOK * OCH];   // [B][tok][och]
__device__ float  g_z  [(size_t)BATCH * NTOK];         // rowsum(P') via atomics
__device__ float  g_rv [(size_t)BATCH * NTOK];         // v[n] + c0 (row bias of S)
__device__ float  g_cu [(size_t)BATCH * NTOK];         // u[m]      (col bias of S)
__device__ __half g_wqh[(size_t)OCH * CIN];            // Wq half
__device__ __half g_wkh[(size_t)OCH * CIN];            // Wk half
__device__ __half g_wvh[(size_t)OCH * CIN];            // Wv half
__device__ __half g_woh[(size_t)OCH * OCH];            // Wo half
__device__ __half g_mp [(size_t)MSPLIT * CIN * CIN];   // M split-K partials
__device__ __half g_mh [(size_t)CIN * CIN];            // M = Wq^T Wk (half)
__device__ float  g_wv [CIN];                           // Wq^T bk
__device__ float  g_wu [CIN];                           // Wk^T bq
__device__ float  g_c0 [1];                             // bq . bk

// ---------------------------------------------------------------------------
// Fork-join resources, created once at program init (no device-memory alloc).
// If creation fails, everything falls back to the legacy stream serially.
// ---------------------------------------------------------------------------
struct OvlCtx {
    cudaStream_t s2 = nullptr;
    cudaEvent_t evFork = nullptr, evPack = nullptr, evX = nullptr, evV = nullptr;
    bool ok = false;
    OvlCtx() {
        ok = (cudaStreamCreateWithFlags(&s2, cudaStreamNonBlocking) == cudaSuccess) &&
             (cudaEventCreateWithFlags(&evFork, cudaEventDisableTiming) == cudaSuccess) &&
             (cudaEventCreateWithFlags(&evPack, cudaEventDisableTiming) == cudaSuccess) &&
             (cudaEventCreateWithFlags(&evX,    cudaEventDisableTiming) == cudaSuccess) &&
             (cudaEventCreateWithFlags(&evV,    cudaEventDisableTiming) == cudaSuccess);
        if (!ok) s2 = nullptr;
    }
};
static OvlCtx g_ovl;

// ---------------------------------------------------------------------------
// Helpers
// ---------------------------------------------------------------------------
__device__ __forceinline__ uint32_t smem_u32(const void* p) {
    uint32_t a;
    asm("{ .reg .u64 t; cvta.to.shared.u64 t, %1; cvt.u32.u64 %0, t; }" : "=r"(a) : "l"(p));
    return a;
}
__device__ __forceinline__ void ldsm4(uint32_t r[4], uint32_t addr) {
    asm volatile("ldmatrix.sync.aligned.m8n8.x4.shared.b16 {%0,%1,%2,%3}, [%4];"
                 : "=r"(r[0]), "=r"(r[1]), "=r"(r[2]), "=r"(r[3]) : "r"(addr));
}
__device__ __forceinline__ void ldsm4t(uint32_t r[4], uint32_t addr) {
    asm volatile("ldmatrix.sync.aligned.m8n8.x4.trans.shared.b16 {%0,%1,%2,%3}, [%4];"
                 : "=r"(r[0]), "=r"(r[1]), "=r"(r[2]), "=r"(r[3]) : "r"(addr));
}
__device__ __forceinline__ void mma16816(float c[4], const uint32_t a[4],
                                         uint32_t b0, uint32_t b1) {
    asm volatile(
        "mma.sync.aligned.m16n8k16.row.col.f32.f16.f16.f32 "
        "{%0,%1,%2,%3}, {%4,%5,%6,%7}, {%8,%9}, {%0,%1,%2,%3};"
        : "+f"(c[0]), "+f"(c[1]), "+f"(c[2]), "+f"(c[3])
        : "r"(a[0]), "r"(a[1]), "r"(a[2]), "r"(a[3]), "r"(b0), "r"(b1));
}
__device__ __forceinline__ void cp16(uint32_t saddr, const void* gaddr) {
    asm volatile("cp.async.cg.shared.global [%0], [%1], 16;" :: "r"(saddr), "l"(gaddr));
}
__device__ __forceinline__ void cp_commit() { asm volatile("cp.async.commit_group;"); }
template <int N>
__device__ __forceinline__ void cp_waitg() {
    asm volatile("cp.async.wait_group %0;" :: "n"(N) : "memory");
}

// ---------------------------------------------------------------------------
// cp.async staging. TRT=0: NT tile [128][SNT] from [r][k] src.
// TRT=1: TR tile [32][STR] from [k][r] src (r contiguous).
// ---------------------------------------------------------------------------
template <int TRT>
__device__ __forceinline__ void cp_stage(uint32_t sbase, const __half* __restrict__ S,
                                         int ld, int r0, int kt, int tid)
{
    if (TRT == 0) {
#pragma unroll
        for (int i = 0; i < 4; i++) {
            const int idx = tid + i * 128;
            const int r = idx >> 2, c8 = (idx & 3) * 8;
            cp16(sbase + (uint32_t)(r * SNT + c8) * 2, &S[(size_t)(r0 + r) * ld + kt + c8]);
        }
    } else {
#pragma unroll
        for (int i = 0; i < 4; i++) {
            const int idx = tid + i * 128;
            const int k = idx >> 4, c8 = (idx & 15) * 8;
            cp16(sbase + (uint32_t)(k * STR + c8) * 2, &S[(size_t)(kt + k) * ld + r0 + c8]);
        }
    }
}

// ---------------------------------------------------------------------------
// One 128x128x32 tile step. Warp tile 64x64 via m16n8k16 + ldmatrix.
// Mode: 0 = NT tile (ldsm4), 3 = TR tile (ldsm4t).
// ---------------------------------------------------------------------------
template <int AM, int BM>
__device__ __forceinline__ void compute_bk(uint32_t sa, uint32_t sb,
                                           float acc[4][8][4], int lane, int wm, int wn)
{
    constexpr bool ATR = (AM == 3), BTR = (BM == 3);
#pragma unroll
    for (int ks = 0; ks < 32; ks += 16) {
        uint32_t a[4][4];
#pragma unroll
        for (int mb = 0; mb < 4; mb++) {
            if (!ATR) {
                const int row = wm + mb * 16 + (lane & 15);
                const int col = ks + ((lane >> 4) << 3);
                ldsm4(a[mb], sa + (uint32_t)(row * SNT + col) * 2);
            } else {
                const int k   = ks + (lane & 7) + ((lane & 16) >> 1);
                const int col = wm + mb * 16 + (lane & 8);
                ldsm4t(a[mb], sa + (uint32_t)(k * STR + col) * 2);
            }
        }
        uint32_t bfr[4][4];
#pragma unroll
        for (int nb2 = 0; nb2 < 4; nb2++) {
            if (!BTR) {
                const int row = wn + nb2 * 16 + (lane & 15);
                const int col = ks + ((lane >> 4) << 3);
                ldsm4(bfr[nb2], sb + (uint32_t)(row * SNT + col) * 2);
            } else {
                const int k   = ks + (lane & 7) + (lane & 8);
                const int col = wn + nb2 * 16 + ((lane & 16) >> 1);
                ldsm4t(bfr[nb2], sb + (uint32_t)(k * STR + col) * 2);
            }
        }
#pragma unroll
        for (int mb = 0; mb < 4; mb++)
#pragma unroll
            for (int nb = 0; nb < 8; nb++) {
                uint32_t b0, b1;
                if (!BTR) { b0 = bfr[nb >> 1][nb & 1];       b1 = bfr[nb >> 1][(nb & 1) + 2]; }
                else      { b0 = bfr[nb >> 1][2 * (nb & 1)]; b1 = bfr[nb >> 1][2 * (nb & 1) + 1]; }
                mma16816(acc[mb][nb], a[mb], b0, b1);
            }
    }
}

// ---------------------------------------------------------------------------
// Universal batched all-f16 GEMM:
//   C[m][n] = f((acc + biases) * scale)
// AM/BM: 0 = f16 NT, 3 = f16 TR (both cp.async 4-stage).
// OUTH: 1 = half out. BIAS: 0 none, 1 row add, 2 col add, 3 row DIVIDE (by Z),
//       4 row add (bias) + col add (bias2).
// EXPM: 1 = __expf after scale. SUMZ: 1 = atomic row sums into zsum.
// The z grid dim + (sA,sB,sC) strides also express split-K (slice offsets).
// ---------------------------------------------------------------------------
template <int AM, int BM, int OUTH, int BIAS, int EXPM, int SUMZ>
__global__ __launch_bounds__(NTHREADS, 2)
void hgemm(const __half* __restrict__ A, const __half* __restrict__ B, void* __restrict__ C,
           int K, int ldA, int ldB, int ldC,
           size_t sA, size_t sB, size_t sC,
           const float* __restrict__ bias, const float* __restrict__ bias2,
           float* __restrict__ zsum, size_t sBias, float scale)
{
    extern __shared__ __half dsm[];

    const int tid = threadIdx.x;
    const int warp = tid >> 5, lane = tid & 31;
    const int wm = (warp >> 1) * 64, wn = (warp & 1) * 64;
    const int b = blockIdx.z;
    const int row0 = blockIdx.y * 128;
    const int col0 = blockIdx.x * 128;

    const __half* Ab = A + (size_t)b * sA;
    const __half* Bb = B + (size_t)b * sB;
    const float* biasb  = bias  ? bias  + (size_t)b * sBias : nullptr;
    const float* bias2b = bias2 ? bias2 + (size_t)b * sBias : nullptr;
    float* zsumb = zsum ? zsum + (size_t)b * sBias : nullptr;

    const uint32_t uA = smem_u32(dsm);
    const uint32_t uB = uA + NSTAGE * SLOTB;

    float acc[4][8][4];
#pragma unroll
    for (int i = 0; i < 4; i++)
#pragma unroll
        for (int j = 0; j < 8; j++)
#pragma unroll
            for (int q = 0; q < 4; q++) acc[i][j][q] = 0.f;

    const int T = K / 32;

    // Prologue: fill stages 0..2
#pragma unroll
    for (int s = 0; s < NSTAGE - 1; s++) {
        cp_stage<(AM == 3)>(uA + s * SLOTB, Ab, ldA, row0, s * 32, tid);
        cp_stage<(BM == 3)>(uB + s * SLOTB, Bb, ldB, col0, s * 32, tid);
        cp_commit();
    }

    for (int t = 0; t < T; t++) {
        cp_waitg<NSTAGE - 2>();
        __syncthreads();

        const int p = t & (NSTAGE - 1);
        const int tn = t + NSTAGE - 1;
        if (tn < T) {
            const int pn = tn & (NSTAGE - 1);
            cp_stage<(AM == 3)>(uA + pn * SLOTB, Ab, ldA, row0, tn * 32, tid);
            cp_stage<(BM == 3)>(uB + pn * SLOTB, Bb, ldB, col0, tn * 32, tid);
        }
        cp_commit();   // empty group at tail keeps FIFO accounting uniform

        compute_bk<AM, BM>(uA + p * SLOTB, uB + p * SLOTB, acc, lane, wm, wn);
    }

    // Epilogue
#pragma unroll
    for (int mb = 0; mb < 4; mb++) {
        const int m0 = row0 + wm + mb * 16 + (lane >> 2);
        const float ar0 = (BIAS == 1 || BIAS == 4) ? biasb[m0] : 0.f;
        const float ar1 = (BIAS == 1 || BIAS == 4) ? biasb[m0 + 8] : 0.f;
        const float rs0 = (BIAS == 3) ? (1.0f / biasb[m0]) : 1.f;
        const float rs1 = (BIAS == 3) ? (1.0f / biasb[m0 + 8]) : 1.f;
        float s0 = 0.f, s1 = 0.f;
#pragma unroll
        for (int nb = 0; nb < 8; nb++) {
            const int n = col0 + wn + nb * 8 + 2 * (lane & 3);
            float ac0 = 0.f, ac1 = 0.f;
            if (BIAS == 2) { ac0 = biasb[n]; ac1 = biasb[n + 1]; }
            if (BIAS == 4) { ac0 = bias2b[n]; ac1 = bias2b[n + 1]; }
            float v0 = (acc[mb][nb][0] + ar0 + ac0) * scale;
            float v1 = (acc[mb][nb][1] + ar0 + ac1) * scale;
            float v2 = (acc[mb][nb][2] + ar1 + ac0) * scale;
            float v3 = (acc[mb][nb][3] + ar1 + ac1) * scale;
            if (EXPM) { v0 = __expf(v0); v1 = __expf(v1); v2 = __expf(v2); v3 = __expf(v3); }
            if (BIAS == 3) { v0 *= rs0; v1 *= rs0; v2 *= rs1; v3 *= rs1; }
            if (SUMZ) { s0 += v0 + v1; s1 += v2 + v3; }
            if (OUTH) {
                __half* Ch = (__half*)C + (size_t)b * sC;
                *reinterpret_cast<__half2*>(&Ch[(size_t)m0 * ldC + n])       = __floats2half2_rn(v0, v1);
                *reinterpret_cast<__half2*>(&Ch[(size_t)(m0 + 8) * ldC + n]) = __floats2half2_rn(v2, v3);
            } else {
                float* Cf = (float*)C + (size_t)b * sC;
                *reinterpret_cast<float2*>(&Cf[(size_t)m0 * ldC + n])       = make_float2(v0, v1);
                *reinterpret_cast<float2*>(&Cf[(size_t)(m0 + 8) * ldC + n]) = make_float2(v2, v3);
            }
        }
        if (SUMZ) {
            s0 += __shfl_xor_sync(0xffffffffu, s0, 1);
            s0 += __shfl_xor_sync(0xffffffffu, s0, 2);
            s1 += __shfl_xor_sync(0xffffffffu, s1, 1);
            s1 += __shfl_xor_sync(0xffffffffu, s1, 2);
            if ((lane & 3) == 0) {
                atomicAdd(&zsumb[m0], s0);
                atomicAdd(&zsumb[m0 + 8], s1);
            }
        }
    }
}

// ---------------------------------------------------------------------------
// Pack weights -> half; zero Z.
// ---------------------------------------------------------------------------
__global__ __launch_bounds__(256)
void pack_kernel(const float* __restrict__ Wq, const float* __restrict__ Wk,
                 const float* __restrict__ Wv, const float* __restrict__ Wo,
                 __half* __restrict__ wqh, __half* __restrict__ wkh,
                 __half* __restrict__ wvh, __half* __restrict__ woh,
                 float* __restrict__ Z)
{
    const int i = blockIdx.x * 256 + threadIdx.x;
    if (i < OCH * CIN) {
        wqh[i] = __float2half_rn(Wq[i]);
        wkh[i] = __float2half_rn(Wk[i]);
        wvh[i] = __float2half_rn(Wv[i]);
    }
    if (i < OCH * OCH) woh[i] = __float2half_rn(Wo[i]);
    if (i < BATCH * NTOK) Z[i] = 0.f;
}

// ---------------------------------------------------------------------------
// Reduce MSPLIT half partials -> half M. 8 halves (uint4) per thread.
// ---------------------------------------------------------------------------
__global__ __launch_bounds__(256)
void mred_kernel(const __half* __restrict__ mp, __half* __restrict__ mh)
{
    const int i = blockIdx.x * 256 + threadIdx.x;   // uint4 index
    constexpr int NU = CIN * CIN / 8;
    if (i >= NU) return;
    float acc[8];
#pragma unroll
    for (int q = 0; q < 8; q++) acc[q] = 0.f;
#pragma unroll
    for (int s = 0; s < MSPLIT; s++) {
        const uint4 u = reinterpret_cast<const uint4*>(mp + (size_t)s * CIN * CIN)[i];
        const __half2* h = reinterpret_cast<const __half2*>(&u);
#pragma unroll
        for (int q = 0; q < 4; q++) {
            const float2 f = __half22float2(h[q]);
            acc[2 * q] += f.x; acc[2 * q + 1] += f.y;
        }
    }
    uint4 o;
    __half2* oh = reinterpret_cast<__half2*>(&o);
#pragma unroll
    for (int q = 0; q < 4; q++) oh[q] = __floats2half2_rn(acc[2 * q], acc[2 * q + 1]);
    reinterpret_cast<uint4*>(mh)[i] = o;
}

// ---------------------------------------------------------------------------
// w_v = Wq^T bk, w_u = Wk^T bq, c0 = bq.bk
// grid = 3 blocks x 512 threads: 128 i-columns per block, 4 o-groups of 128.
// ---------------------------------------------------------------------------
__global__ __launch_bounds__(512)
void uvw_kernel(const float* __restrict__ Wq, const float* __restrict__ Wk,
                const float* __restrict__ bq, const float* __restrict__ bk,
                float* __restrict__ wv, float* __restrict__ wu, float* __restrict__ c0)
{
    __shared__ float sv[4][128], su[4][128], red[256];
    const int t = threadIdx.x & 127, g = threadIdx.x >> 7;
    const int i = blockIdx.x * 128 + t;

    float av = 0.f, au = 0.f;
#pragma unroll 4
    for (int o = g * 128; o < (g + 1) * 128; o++) {
        av += Wq[(size_t)o * CIN + i] * bk[o];
        au += Wk[(size_t)o * CIN + i] * bq[o];
    }
    sv[g][t] = av; su[g][t] = au;

    if (threadIdx.x < 256)
        red[threadIdx.x] = bq[threadIdx.x] * bk[threadIdx.x]
                         + bq[threadIdx.x + 256] * bk[threadIdx.x + 256];
    __syncthreads();

    if (g == 0) {
        wv[i] = sv[0][t] + sv[1][t] + sv[2][t] + sv[3][t];
        wu[i] = su[0][t] + su[1][t] + su[2][t] + su[3][t];
    }
    for (int s = 128; s > 0; s >>= 1) {
        if (threadIdx.x < s) red[threadIdx.x] += red[threadIdx.x + s];
        __syncthreads();
    }
    if (blockIdx.x == 0 && threadIdx.x == 0) c0[0] = red[0];
}

// ---------------------------------------------------------------------------
// Fused x convert + rank-1 terms. One pass over x:
//   xh = half(x); rv[b][n] = w_v.x_n + c0; cu[b][n] = w_u.x_n
// grid = B*NTOK/64 = 288 blocks x 512 threads: 64 tokens, 8 channel groups of 48.
// ---------------------------------------------------------------------------
__global__ __launch_bounds__(512)
void xuv_kernel(const float* __restrict__ x, __half* __restrict__ xh,
                const float* __restrict__ wv, const float* __restrict__ wu,
                const float* __restrict__ c0,
                float* __restrict__ rv, float* __restrict__ cu)
{
    __shared__ float swv[CIN], swu[CIN];
    __shared__ float redv[8][64], redu[8][64];
    const int tid = threadIdx.x;
    if (tid < CIN) { swv[tid] = wv[tid]; swu[tid] = wu[tid]; }
    __syncthreads();

    const int tile = blockIdx.x;
    const int b = tile / (NTOK / 64);
    const int n0 = (tile % (NTOK / 64)) * 64;
    const size_t base = (size_t)b * CIN * NTOK;
    const float* xb = x + base;
    __half* xhb = xh + base;
    const int t = tid & 63, g = tid >> 6;

    float sv = 0.f, su = 0.f;
#pragma unroll 6
    for (int c = g * 48; c < (g + 1) * 48; c++) {
        const size_t off = (size_t)c * NTOK + n0 + t;
        const float xv = xb[off];
        xhb[off] = __float2half_rn(xv);
        sv += swv[c] * xv;
        su += swu[c] * xv;
    }
    redv[g][t] = sv; redu[g][t] = su;
    __syncthreads();

    if (g == 0) {
        const int idx = b * NTOK + n0 + t;
        float av = 0.f, au = 0.f;
#pragma unroll
        for (int q = 0; q < 8; q++) { av += redv[q][t]; au += redu[q][t]; }
        rv[idx] = av + c0[0];
        cu[idx] = au;
    }
}

// ---------------------------------------------------------------------------
extern "C" void kernel_launch(void* const* d_in, const int* in_sizes, int n_in,
                              void* d_out, int out_size)
{
    const float* x  = (const float*)d_in[0];
    const float* Wq = (const float*)d_in[1];
    const float* bq = (const float*)d_in[2];
    const float* Wk = (const float*)d_in[3];
    const float* bk = (const float*)d_in[4];
    const float* Wv = (const float*)d_in[5];
    const float* bv = (const float*)d_in[6];
    const float* Wo = (const float*)d_in[7];
    const float* bo = (const float*)d_in[8];
    float* out = (float*)d_out;

    __half *xh, *yh, *vh, *p, *ao, *wqh, *wkh, *wvh, *woh, *mp, *mh;
    float *z, *rv, *cu, *wv, *wu, *c0;
    cudaGetSymbolAddress((void**)&xh,  g_xh);
    cudaGetSymbolAddress((void**)&yh,  g_yh);
    cudaGetSymbolAddress((void**)&vh,  g_vh);
    cudaGetSymbolAddress((void**)&p,   g_p);
    cudaGetSymbolAddress((void**)&ao,  g_ao);
    cudaGetSymbolAddress((void**)&z,   g_z);
    cudaGetSymbolAddress((void**)&rv,  g_rv);
    cudaGetSymbolAddress((void**)&cu,  g_cu);
    cudaGetSymbolAddress((void**)&wqh, g_wqh);
    cudaGetSymbolAddress((void**)&wkh, g_wkh);
    cudaGetSymbolAddress((void**)&wvh, g_wvh);
    cudaGetSymbolAddress((void**)&woh, g_woh);
    cudaGetSymbolAddress((void**)&mp,  g_mp);
    cudaGetSymbolAddress((void**)&mh,  g_mh);
    cudaGetSymbolAddress((void**)&wv,  g_wv);
    cudaGetSymbolAddress((void**)&wu,  g_wu);
    cudaGetSymbolAddress((void**)&c0,  g_c0);

    cudaFuncSetAttribute(hgemm<3,3,1,0,0,0>, cudaFuncAttributeMaxDynamicSharedMemorySize, SMEM_BYTES);
    cudaFuncSetAttribute(hgemm<3,0,1,2,0,0>, cudaFuncAttributeMaxDynamicSharedMemorySize, SMEM_BYTES);
    cudaFuncSetAttribute(hgemm<0,3,1,0,0,0>, cudaFuncAttributeMaxDynamicSharedMemorySize, SMEM_BYTES);
    cudaFuncSetAttribute(hgemm<3,3,1,4,1,1>, cudaFuncAttributeMaxDynamicSharedMemorySize, SMEM_BYTES);
    cudaFuncSetAttribute(hgemm<0,3,1,3,0,0>, cudaFuncAttributeMaxDynamicSharedMemorySize, SMEM_BYTES);
    cudaFuncSetAttribute(hgemm<0,0,0,1,0,0>, cudaFuncAttributeMaxDynamicSharedMemorySize, SMEM_BYTES);

    const bool ovl = g_ovl.ok;
    cudaStream_t sL = (cudaStream_t)0;            // legacy stream (captured by harness)
    cudaStream_t s2 = ovl ? g_ovl.s2 : sL;        // fallback: everything serial on legacy

    const dim3 blk(NTHREADS);
    const size_t sX  = (size_t)CIN * NTOK;
    const size_t sY  = (size_t)CIN * NTOK;
    const size_t sV  = (size_t)NTOK * OCH;
    const size_t sS  = (size_t)NTOK * NTOK;
    const size_t sAO = (size_t)NTOK * OCH;
    const float scale = 0.044194173824159216f; // 1/sqrt(512)

    // Fork: make s2 part of the capture graph.
    if (ovl) {
        cudaEventRecord(g_ovl.evFork, sL);
        cudaStreamWaitEvent(s2, g_ovl.evFork, 0);
    }

    // L: pack (weights -> half, zero Z)
    pack_kernel<<<(OCH * OCH + 255) / 256, 256, 0, sL>>>(Wq, Wk, Wv, Wo, wqh, wkh, wvh, woh, z);
    if (ovl) cudaEventRecord(g_ovl.evPack, sL);

    // s2: rank-1 vectors + fused x-convert (independent of pack)
    uvw_kernel<<<CIN / 128, 512, 0, s2>>>(Wq, Wk, bq, bk, wv, wu, c0);
    xuv_kernel<<<BATCH * NTOK / 64, 512, 0, s2>>>(x, xh, wv, wu, c0, rv, cu);
    if (ovl) cudaEventRecord(g_ovl.evX, s2);

    // s2: V projection (needs wvh from pack + xh) — overlaps M/mred/Y/S on L
    if (ovl) cudaStreamWaitEvent(s2, g_ovl.evPack, 0);
    {
        dim3 g(OCH / 128, NTOK / 128, BATCH);
        hgemm<3,0,1,2,0,0><<<g, blk, SMEM_BYTES, s2>>>(xh, wvh, vh, CIN, NTOK, CIN, OCH,
                                                       sX, 0, sV, bv, nullptr, nullptr, 0, 1.0f);
    }
    if (ovl) cudaEventRecord(g_ovl.evV, s2);

    // L: M = Wq^T Wk, split-K over z (4 slices of 128), then reduce
    {
        dim3 g(CIN / 128, CIN / 128, MSPLIT);
        hgemm<3,3,1,0,0,0><<<g, blk, SMEM_BYTES, sL>>>(wqh, wkh, mp, OCH / MSPLIT, CIN, CIN, CIN,
                                                       (size_t)(OCH / MSPLIT) * CIN,
                                                       (size_t)(OCH / MSPLIT) * CIN,
                                                       (size_t)CIN * CIN,
                                                       nullptr, nullptr, nullptr, 0, 1.0f);
        mred_kernel<<<(CIN * CIN / 8 + 255) / 256, 256, 0, sL>>>(mp, mh);
    }

    // L: Y = M x  (needs xh -> wait evX)
    if (ovl) cudaStreamWaitEvent(sL, g_ovl.evX, 0);
    {
        dim3 g(NTOK / 128, CIN / 128, BATCH);
        hgemm<0,3,1,0,0,0><<<g, blk, SMEM_BYTES, sL>>>(mh, xh, yh, CIN, CIN, NTOK, NTOK,
                                                       0, sX, sY, nullptr, nullptr, nullptr, 0, 1.0f);
    }
    // L: P' = exp(scale*(x^T Y + rv[n] + cu[m]))  (K=384, fused exp + atomic Z)
    {
        dim3 g(NTOK / 128, NTOK / 128, BATCH);
        hgemm<3,3,1,4,1,1><<<g, blk, SMEM_BYTES, sL>>>(xh, yh, p, CIN, NTOK, NTOK, NTOK,
                                                       sX, sY, sS, rv, cu, z, NTOK, scale);
    }
    // L: AO = (P' V) / Z  (needs V -> wait evV)
    if (ovl) cudaStreamWaitEvent(sL, g_ovl.evV, 0);
    {
        dim3 g(OCH / 128, NTOK / 128, BATCH);
        hgemm<0,3,1,3,0,0><<<g, blk, SMEM_BYTES, sL>>>(p, vh, ao, NTOK, NTOK, OCH, OCH,
                                                       sS, sV, sAO, z, nullptr, nullptr, NTOK, 1.0f);
    }
    // L: out = Wo AO^T + bo
    {
        dim3 g(NTOK / 128, OCH / 128, BATCH);
        hgemm<0,0,0,1,0,0><<<g, blk, SMEM_BYTES, sL>>>(woh, ao, out, OCH, OCH, OCH, NTOK,
                                                       0, sAO, (size_t)OCH * NTOK, bo, nullptr, nullptr, 0, 1.0f);
    }
}